// round 13
// baseline (speedup 1.0000x reference)
#include <cuda_runtime.h>

#define THREADS 256
#define Jt 32
#define NT 32          // 1024 / Jt
#define DEPTH 3
#define TILEB (Jt * 17 * 16)     // 8704 bytes per smem tile slot

typedef unsigned long long u64;
typedef unsigned int u32;

#define FMA2(d,a,b,c)  asm("fma.rn.f32x2 %0, %1, %2, %3;" : "=l"(d) : "l"(a), "l"(b), "l"(c))
#define PACK2(d,x,y)   asm("mov.b64 %0, {%1,%2};" : "=l"(d) : "f"(x), "f"(y))
#define UNPACK2(x,y,d) asm("mov.b64 {%0,%1}, %2;" : "=f"(x), "=f"(y) : "l"(d))
#define CVTH2(h,la,lb) asm("cvt.rn.f16x2.f32 %0, %1, %2;" : "=r"(h) : "f"(lb), "f"(la))
#define TANH2H(d,a)    asm("tanh.approx.f16x2 %0, %1;" : "=r"(d) : "r"(a))
#define HFMA2(d,a,b,c) asm("fma.rn.f16x2 %0, %1, %2, %3;" : "=r"(d) : "r"(a), "r"(b), "r"(c))
#define H2TOF2(x,y,h)  asm("{ .reg .f16 lo, hi;\n\t mov.b32 {lo, hi}, %2;\n\t" \
                           "  cvt.f32.f16 %0, lo;\n\t cvt.f32.f16 %1, hi; }" \
                           : "=f"(x), "=f"(y) : "r"(h))
#define CP16O(dst,doff,src,soff) \
    asm volatile("cp.async.cg.shared.global [%0+" #doff "], [%1+" #soff "], 16;" \
                 :: "r"(dst), "l"(src))
#define CPCOMMIT()     asm volatile("cp.async.commit_group;")
#define CPWAIT1()      asm volatile("cp.async.wait_group 1;")

__global__ __launch_bounds__(THREADS, 3)
void attn_mlp_kernel(const float* __restrict__ Q, const float* __restrict__ K,
                     const float* __restrict__ bias, const float* __restrict__ mask,
                     float* __restrict__ out, float* __restrict__ attn)
{
    __shared__ float4 ksm[DEPTH][Jt * 17];   // K tile ring, pad 17 -> conflict-free
    __shared__ float  red[8 * 64];           // [warp][ch]
    __shared__ float  cbuf[8];

    const int tid = threadIdx.x;
    const int w   = tid >> 5, l = tid & 31;
    const int r   = w >> 2;              // row handled by this warp (0/1)
    const int jl  = (w & 3) * 8 + (l & 7);   // j within tile (0..31)
    const int cg  = l >> 3;              // channel group (16 ch each)

    const int row0 = blockIdx.x * 2;     // two i-rows per block, same b
    const int row  = row0 + r;
    const int b    = row0 >> 10;

    // q prescaled by 0.5 (sigmoid = 0.5 + 0.5*tanh(x/2)), bias likewise; f32x2 packed
    u64 q2[8], b2[8];
    u32 h[8];                            // f16x2 accumulators, whole-row (no flush)
    {
        const float* qp = Q + (size_t)row * 64 + cg * 16;
        const float* bp = bias + cg * 16;
#pragma unroll
        for (int p = 0; p < 8; ++p) {
            PACK2(q2[p], 0.5f * qp[2*p], 0.5f * qp[2*p+1]);
            PACK2(b2[p], 0.5f * bp[2*p], 0.5f * bp[2*p+1]);
            h[p] = 0u;
        }
    }
    float cnt = 0.f;

    const float* mrow = mask + (size_t)row * 1024;
    float*       arow = attn + (size_t)row * 1024;

    // cp.async staging: 2 float4/thread/tile; one dst base + one src ptr, imm offsets
    const u32 smbase = (u32)__cvta_generic_to_shared(ksm);
    const u32 dst0   = smbase + (u32)((((tid >> 4) * 17 + (tid & 15))) << 4);
    const char* src  = (const char*)K + (size_t)b * (1024 * 256)
                       + (((tid >> 4) * 16 + (tid & 15)) << 4);

    // prologue: tiles 0 and 1 (two groups)
#pragma unroll
    for (int t = 0; t < 2; ++t) {
        u32 d = dst0 + t * TILEB;
        const char* s = src + t * 8192;
        CP16O(d, 0,    s, 0);
        CP16O(d, 4352, s, 4096);     // +16 rows: dst +16*17*16, src +16*16*16
        CPCOMMIT();
    }
    src += 2 * 8192;

    int buf = 0, nb = 2;
    for (int tile = 0; tile < NT; ++tile) {
        CPWAIT1();            // this tile's group complete (<=1 newer pending)
        __syncthreads();

        // prefetch tile+2 into ring slot nb (empty commit keeps group count in sync)
        if (tile + 2 < NT) {
            u32 d = dst0 + nb * TILEB;
            CP16O(d, 0,    src, 0);
            CP16O(d, 4352, src, 4096);
        }
        CPCOMMIT();
        src += 8192;

        // 16 channels for this thread's j, straight from padded smem as u64 pairs
        const u64* kb = (const u64*)(ksm[buf]) + jl * 34 + cg * 8;
        u64 k2[8];
#pragma unroll
        for (int p = 0; p < 8; ++p) k2[p] = kb[p];

        const int   j = tile * Jt + jl;
        const float m = mrow[j];
        u32 mh; CVTH2(mh, m, m);         // mask 0/1 exact in f16
        u64 dp = 0ull;

#pragma unroll
        for (int p = 0; p < 8; ++p) {
            u64 l2; float la, lb; u32 hh, th;
            FMA2(l2, q2[p], k2[p], b2[p]);   // f32 logit (prescaled 0.5)
            FMA2(dp, q2[p], k2[p], dp);      // f32 dot partial (exact attn path)
            UNPACK2(la, lb, l2);
            CVTH2(hh, la, lb);               // one F2FP
            TANH2H(th, hh);                  // ONE XU inst, two elements
            HFMA2(h[p], mh, th, h[p]);       // f16x2 accumulate (FMA pipe)
        }
        cnt += m;                            // 4x cg duplication fixed by 0.25 later

        // attention logits: q prescaled by 0.5 -> attn = 2*dot*mask (exact fp32 path)
        float dx, dy;
        UNPACK2(dx, dy, dp);
        float d = dx + dy;
        d += __shfl_xor_sync(~0u, d, 8);
        d += __shfl_xor_sync(~0u, d, 16);
        if (l < 8)
            arow[j] = (d + d) * m;

        buf = (buf == DEPTH - 1) ? 0 : buf + 1;
        nb  = (nb  == DEPTH - 1) ? 0 : nb + 1;
    }

    // ---- final reductions ----
    // convert f16x2 accumulators, sum over the 8 j-lanes sharing this cg (xor 1,2,4)
#pragma unroll
    for (int p = 0; p < 8; ++p) {
        float x, y;
        H2TOF2(x, y, h[p]);
#pragma unroll
        for (int o = 1; o <= 4; o <<= 1) {
            x += __shfl_xor_sync(~0u, x, o);
            y += __shfl_xor_sync(~0u, y, o);
        }
        if ((l & 7) == 0) {
            float* rp = red + w * 64 + cg * 16 + 2 * p;
            rp[0] = x;
            rp[1] = y;
        }
    }
    // mask count: warp-sum counts each j 4x (once per cg lane)
#pragma unroll
    for (int o = 1; o <= 16; o <<= 1)
        cnt += __shfl_xor_sync(~0u, cnt, o);
    if (l == 0) cbuf[w] = cnt;
    __syncthreads();

    if (tid < 128) {
        const int rr = tid >> 6;
        const int ch = tid & 63;
        float ct = 0.25f * (cbuf[rr*4] + cbuf[rr*4+1] + cbuf[rr*4+2] + cbuf[rr*4+3]);
        float s  = red[(rr*4)   * 64 + ch] + red[(rr*4+1) * 64 + ch]
                 + red[(rr*4+2) * 64 + ch] + red[(rr*4+3) * 64 + ch];
        out[(size_t)(row0 + rr) * 64 + ch] = 0.5f + 0.5f * s / ct;
    }
}

extern "C" void kernel_launch(void* const* d_in, const int* in_sizes, int n_in,
                              void* d_out, int out_size)
{
    const float* Q    = (const float*)d_in[0];
    const float* K    = (const float*)d_in[1];
    const float* bias = (const float*)d_in[2];
    const float* mask = (const float*)d_in[3];
    float* out  = (float*)d_out;                       // [B, I, C]
    float* attn = out + (size_t)2 * 1024 * 64;         // [B, I, J]
    attn_mlp_kernel<<<1024, THREADS>>>(Q, K, bias, mask, out, attn);
}